// round 6
// baseline (speedup 1.0000x reference)
#include <cuda_runtime.h>
#include <cuda_bf16.h>
#include <math.h>

// Problem constants (fixed by the dataset)
#define BB 8
#define NN 2000
#define CC 81
#define IOU_THR 0.5f
#define CLASS_OFFSET 100000.0f
#define CAP 96                  // per-(batch,class) bucket capacity (mean ~25, +14 sigma)
#define NROWS (BB * NN)         // 16000
#define NTASK (BB * (CC - 1))   // 640 NMS tasks

#define TPB 256
#define WPB 8                   // warps per block
#define PREP_BLOCKS 1000        // 1000 blocks * 8 warps * 2 rows = 16000 rows exactly
#define NMS_BLOCKS 80           // last 80 blocks also run NMS: 80*8 = 640 tasks
#define NMS_FIRST (PREP_BLOCKS - NMS_BLOCKS)

// Output layout: concat of reference's 7-tuple, all float32
// (nms_reg, nms_cls, rcnn_reg_adj, probs, reg_out, cls_out, keep)
#define OFF0 0
#define OFF1 (BB*NN*4)
#define OFF2 (OFF1 + BB*NN*2)
#define OFF3 (OFF2 + BB*NN*4)
#define OFF4 (OFF3 + BB*NN*CC)
#define OFF5 (OFF4 + BB*NN*4)
#define OFF6 (OFF5 + BB*NN*CC)

// ---- scratch (device globals; zero-initialized at module load; no allocation) ----
__device__ int                g_cnt[BB*CC];          // bucket counters; nms resets after reading
__device__ unsigned long long g_bucket[BB*CC*CAP];   // composite keys per bucket
__device__ unsigned           g_done;                // prep-complete block counter
__device__ unsigned           g_ndone;               // nms-complete block counter

// reduction input may arrive as int32 or float32; handle both.
__device__ __forceinline__ float read_reduction(const void* p) {
    if (p == nullptr) return 16.0f;
    int iv = *(const int*)p;
    if (iv > 0 && iv < (1 << 20)) return (float)iv;
    return *(const float*)p;
}

// ============================================================
// Fused kernel.
// Part 1 (all 1000 blocks): per-row prep, one warp per TWO rows.
//   softmax -> probs; argmax; speculative masked outputs
//   (k = cls!=0); bucket append. Identical math to the passing
//   33.5us version.
// Part 2 (last 80 blocks): spin until all blocks finished part 1,
//   then bitmask NMS (1 warp per (batch,class) task) + fixup of
//   suppressed rows. Greedy semantics identical to reference
//   (cross-class IoU exactly 0 due to CLASS_OFFSET).
// ============================================================
__global__ __launch_bounds__(TPB)
void fused_kernel(const float* __restrict__ nms_reg,
                  const float* __restrict__ nms_cls,
                  const float* __restrict__ rcnn_reg,
                  const float* __restrict__ rcnn_cls,
                  const void* __restrict__ redp,
                  float* __restrict__ out)
{
    const int lane = threadIdx.x & 31;
    const int wib  = threadIdx.x >> 5;

    // -------------------- Part 1: prep --------------------
    {
        const int gw   = blockIdx.x * WPB + wib;
        const int row0 = gw * 2;
        const int row1 = row0 + 1;

        const bool has2 = (lane < CC - 64);
        const float* cl0 = rcnn_cls + (size_t)row0 * CC;
        const float* cl1 = cl0 + CC;

        float a0 = cl0[lane];
        float a1 = cl0[lane + 32];
        float a2 = has2 ? cl0[lane + 64] : -INFINITY;
        float b0 = cl1[lane];
        float b1 = cl1[lane + 32];
        float b2 = has2 ? cl1[lane + 64] : -INFINITY;

        float mA = fmaxf(a0, fmaxf(a1, a2));
        float mB = fmaxf(b0, fmaxf(b1, b2));
        #pragma unroll
        for (int o = 16; o; o >>= 1) {
            mA = fmaxf(mA, __shfl_xor_sync(0xFFFFFFFFu, mA, o));
            mB = fmaxf(mB, __shfl_xor_sync(0xFFFFFFFFu, mB, o));
        }

        float eA0 = expf(a0 - mA), eA1 = expf(a1 - mA), eA2 = has2 ? expf(a2 - mA) : 0.0f;
        float eB0 = expf(b0 - mB), eB1 = expf(b1 - mB), eB2 = has2 ? expf(b2 - mB) : 0.0f;
        float sA = eA0 + eA1 + eA2;
        float sB = eB0 + eB1 + eB2;
        #pragma unroll
        for (int o = 16; o; o >>= 1) {
            sA += __shfl_xor_sync(0xFFFFFFFFu, sA, o);
            sB += __shfl_xor_sync(0xFFFFFFFFu, sB, o);
        }

        float pA0 = eA0 / sA, pA1 = eA1 / sA, pA2 = eA2 / sA;
        float pB0 = eB0 / sB, pB1 = eB1 / sB, pB2 = eB2 / sB;

        float* poA = out + OFF3 + (size_t)row0 * CC;
        float* poB = poA + CC;
        poA[lane]      = pA0;
        poA[lane + 32] = pA1;
        if (has2) poA[lane + 64] = pA2;
        poB[lane]      = pB0;
        poB[lane + 32] = pB1;
        if (has2) poB[lane + 64] = pB2;

        float bpA = pA0; int biA = lane;
        if (pA1 > bpA) { bpA = pA1; biA = lane + 32; }
        if (has2 && pA2 > bpA) { bpA = pA2; biA = lane + 64; }
        float bpB = pB0; int biB = lane;
        if (pB1 > bpB) { bpB = pB1; biB = lane + 32; }
        if (has2 && pB2 > bpB) { bpB = pB2; biB = lane + 64; }
        #pragma unroll
        for (int o = 16; o; o >>= 1) {
            float opA = __shfl_xor_sync(0xFFFFFFFFu, bpA, o);
            int   oiA = __shfl_xor_sync(0xFFFFFFFFu, biA, o);
            if (opA > bpA || (opA == bpA && oiA < biA)) { bpA = opA; biA = oiA; }
            float opB = __shfl_xor_sync(0xFFFFFFFFu, bpB, o);
            int   oiB = __shfl_xor_sync(0xFFFFFFFFu, biB, o);
            if (opB > bpB || (opB == bpB && oiB < biB)) { bpB = opB; biB = oiB; }
        }

        const float kA = (biA != 0) ? 1.0f : 0.0f;
        const float kB = (biB != 0) ? 1.0f : 0.0f;

        float* coA = out + OFF5 + (size_t)row0 * CC;
        float* coB = coA + CC;
        coA[lane]      = pA0 * kA;
        coA[lane + 32] = pA1 * kA;
        if (has2) coA[lane + 64] = pA2 * kA;
        coB[lane]      = pB0 * kB;
        coB[lane + 32] = pB1 * kB;
        if (has2) coB[lane + 64] = pB2 * kB;

        if (lane < 2) {
            const int   row = (lane == 0) ? row0 : row1;
            const int   cls = (lane == 0) ? biA  : biB;
            const float bp  = (lane == 0) ? bpA  : bpB;
            const float k   = (lane == 0) ? kA   : kB;
            const float red = read_reduction(redp);

            float4 nr = ((const float4*)nms_reg)[row];
            float rt = floorf(nr.x * red) / red;
            float rl = floorf(nr.y * red) / red;
            float rb = ceilf(nr.z * red) / red;
            float rr = ceilf(nr.w * red) / red;

            float4 rg = ((const float4*)rcnn_reg)[row];
            float4 adj;
            adj.x = rg.x + rt; adj.y = rg.y + rl; adj.z = rg.z + rb; adj.w = rg.w + rr;
            ((float4*)(out + OFF2))[row] = adj;

            float4 ro;
            ro.x = adj.x * k; ro.y = adj.y * k; ro.z = adj.z * k; ro.w = adj.w * k;
            ((float4*)(out + OFF4))[row] = ro;

            ((float4*)(out + OFF0))[row] = nr;
            ((float2*)(out + OFF1))[row] = ((const float2*)nms_cls)[row];

            out[OFF6 + row] = k;

            if (cls != 0) {
                unsigned sb = __float_as_uint(bp);
                unsigned so = (sb & 0x80000000u) ? ~sb : (sb | 0x80000000u);
                unsigned sdesc = ~so;
                int b = row / NN, n = row % NN;
                unsigned long long key = ((unsigned long long)sdesc << 32)
                                       | (unsigned long long)(unsigned)n;
                int bc = b * CC + cls;
                int pos = atomicAdd(&g_cnt[bc], 1);
                if (pos < CAP) g_bucket[(size_t)bc * CAP + pos] = key;
            }
        }
    }

    // publish prep completion
    __syncthreads();
    if (threadIdx.x == 0) {
        __threadfence();
        atomicAdd(&g_done, 1u);
    }

    if (blockIdx.x < NMS_FIRST) return;

    // -------------------- Part 2: NMS (last 80 blocks) --------------------
    __shared__ unsigned long long s_key [WPB][CAP];
    __shared__ float4             s_box [WPB][CAP];
    __shared__ unsigned short     s_sid [WPB][CAP];
    __shared__ uint4              s_rm  [WPB][CAP];

    // wait for all blocks' prep writes to be visible
    if (threadIdx.x == 0) {
        while (atomicAdd(&g_done, 0u) < (unsigned)PREP_BLOCKS) { __nanosleep(128); }
        __threadfence();
    }
    __syncthreads();

    {
        const int task = (blockIdx.x - NMS_FIRST) * WPB + wib;   // 0..639
        const int b  = task / (CC - 1);
        const int c  = task % (CC - 1) + 1;
        const int bc = b * CC + c;

        int n = g_cnt[bc];
        if (lane == 0) g_cnt[bc] = 0;          // reset for next replay
        if (n > CAP) n = CAP;

        if (n > 0) {
            // ---- Phase A: load keys, rank-sort, gather sorted boxes ----
            const unsigned long long* bk = g_bucket + (size_t)bc * CAP;
            for (int j = lane; j < n; j += 32) s_key[wib][j] = bk[j];
            __syncwarp();

            const float off = (float)c * CLASS_OFFSET;
            for (int j = lane; j < n; j += 32) {
                unsigned long long kj = s_key[wib][j];
                int rank = 0;
                for (int kk = 0; kk < n; kk++) rank += (s_key[wib][kk] < kj);
                int idx = (int)(kj & 0xFFFFFFFFu);
                float4 adj = ((const float4*)(out + OFF2))[b * NN + idx];
                float4 ob;
                ob.x = adj.x + off; ob.y = adj.y + off; ob.z = adj.z + off; ob.w = adj.w + off;
                s_sid[wib][rank] = (unsigned short)idx;
                s_box[wib][rank] = ob;
            }
            __syncwarp();

            float4 bx0, bx1, bx2;
            float ar0 = 0.0f, ar1 = 0.0f, ar2 = 0.0f;
            if (lane < n)      { bx0 = s_box[wib][lane];      ar0 = (bx0.z - bx0.x) * (bx0.w - bx0.y); }
            if (lane + 32 < n) { bx1 = s_box[wib][lane + 32]; ar1 = (bx1.z - bx1.x) * (bx1.w - bx1.y); }
            if (lane + 64 < n) { bx2 = s_box[wib][lane + 64]; ar2 = (bx2.z - bx2.x) * (bx2.w - bx2.y); }

            // ---- Phase B: suppression matrix (independent iterations) ----
            for (int i = 0; i < n - 1; i++) {
                float4 bi = s_box[wib][i];
                float areai = (bi.z - bi.x) * (bi.w - bi.y);

                bool sup0 = false, sup1 = false, sup2 = false;
                {
                    int j = lane;
                    if (j < n && j > i) {
                        float it = fmaxf(bi.x, bx0.x);
                        float il = fmaxf(bi.y, bx0.y);
                        float ib = fminf(bi.z, bx0.z);
                        float ir = fminf(bi.w, bx0.w);
                        float inter = fmaxf(ib - it, 0.0f) * fmaxf(ir - il, 0.0f);
                        float uni = areai + ar0 - inter;
                        float iou = inter / fmaxf(uni, 1e-9f);
                        sup0 = (iou > IOU_THR);
                    }
                }
                unsigned w0 = __ballot_sync(0xFFFFFFFFu, sup0);
                unsigned w1 = 0, w2 = 0;
                if (n > 32) {
                    int j = lane + 32;
                    if (j < n && j > i) {
                        float it = fmaxf(bi.x, bx1.x);
                        float il = fmaxf(bi.y, bx1.y);
                        float ib = fminf(bi.z, bx1.z);
                        float ir = fminf(bi.w, bx1.w);
                        float inter = fmaxf(ib - it, 0.0f) * fmaxf(ir - il, 0.0f);
                        float uni = areai + ar1 - inter;
                        float iou = inter / fmaxf(uni, 1e-9f);
                        sup1 = (iou > IOU_THR);
                    }
                    w1 = __ballot_sync(0xFFFFFFFFu, sup1);
                }
                if (n > 64) {
                    int j = lane + 64;
                    if (j < n && j > i) {
                        float it = fmaxf(bi.x, bx2.x);
                        float il = fmaxf(bi.y, bx2.y);
                        float ib = fminf(bi.z, bx2.z);
                        float ir = fminf(bi.w, bx2.w);
                        float inter = fmaxf(ib - it, 0.0f) * fmaxf(ir - il, 0.0f);
                        float uni = areai + ar2 - inter;
                        float iou = inter / fmaxf(uni, 1e-9f);
                        sup2 = (iou > IOU_THR);
                    }
                    w2 = __ballot_sync(0xFFFFFFFFu, sup2);
                }
                if (lane == 0) {
                    uint4 rm; rm.x = w0; rm.y = w1; rm.z = w2; rm.w = 0;
                    s_rm[wib][i] = rm;
                }
            }
            __syncwarp();

            // ---- Phase C: serial bit resolution (registers, warp-uniform) ----
            unsigned k0, k1, k2;
            k0 = (n >= 32) ? 0xFFFFFFFFu : ((1u << n) - 1u);
            k1 = (n >= 64) ? 0xFFFFFFFFu : ((n > 32) ? ((1u << (n - 32)) - 1u) : 0u);
            k2 = (n > 64) ? ((n >= 96) ? 0xFFFFFFFFu : ((1u << (n - 64)) - 1u)) : 0u;

            for (int i = 0; i < n - 1; i++) {
                unsigned word = (i < 32) ? k0 : ((i < 64) ? k1 : k2);
                if ((word >> (i & 31)) & 1u) {
                    uint4 rm = s_rm[wib][i];
                    k0 &= ~rm.x; k1 &= ~rm.y; k2 &= ~rm.z;
                }
            }

            // ---- Phase D: fixup suppressed rows ----
            for (int i = 0; i < n; i++) {
                unsigned word = (i < 32) ? k0 : ((i < 64) ? k1 : k2);
                if (!((word >> (i & 31)) & 1u)) {
                    int row = b * NN + (int)s_sid[wib][i];
                    float* co = out + OFF5 + (size_t)row * CC;
                    for (int t = lane; t < CC; t += 32) co[t] = 0.0f;
                    if (lane == 0) {
                        float4 z; z.x = 0.0f; z.y = 0.0f; z.z = 0.0f; z.w = 0.0f;
                        ((float4*)(out + OFF4))[row] = z;
                        out[OFF6 + row] = 0.0f;
                    }
                }
            }
        }
    }

    // counter self-reset for next graph replay (safe: all nms blocks have
    // passed their spin before the last one performs the reset; replays
    // are serialized by the stream).
    __syncthreads();
    if (threadIdx.x == 0) {
        unsigned r = atomicAdd(&g_ndone, 1u);
        if (r == (unsigned)(NMS_BLOCKS - 1)) {
            atomicExch(&g_ndone, 0u);
            atomicExch(&g_done, 0u);
        }
    }
}

extern "C" void kernel_launch(void* const* d_in, const int* in_sizes, int n_in,
                              void* d_out, int out_size)
{
    const float* nms_reg  = (const float*)d_in[0];
    const float* nms_cls  = (const float*)d_in[1];
    const float* rcnn_reg = (const float*)d_in[2];
    const float* rcnn_cls = (const float*)d_in[3];
    const void*  redp     = (n_in >= 5) ? d_in[4] : nullptr;
    float* out = (float*)d_out;
    (void)in_sizes; (void)out_size;

    fused_kernel<<<PREP_BLOCKS, TPB>>>(nms_reg, nms_cls, rcnn_reg, rcnn_cls, redp, out);
}

// round 7
// speedup vs baseline: 2.1402x; 2.1402x over previous
#include <cuda_runtime.h>
#include <cuda_bf16.h>
#include <math.h>

// Problem constants (fixed by the dataset)
#define BB 8
#define NN 2000
#define CC 81
#define IOU_THR 0.5f
#define CLASS_OFFSET 100000.0f
#define CAP 96                  // per-(batch,class) bucket capacity (mean ~25, +14 sigma)
#define NROWS (BB * NN)         // 16000
#define NTASK (BB * (CC - 1))   // 640 NMS tasks

// Output layout: concat of reference's 7-tuple, all float32
// (nms_reg, nms_cls, rcnn_reg_adj, probs, reg_out, cls_out, keep)
#define OFF0 0
#define OFF1 (BB*NN*4)
#define OFF2 (OFF1 + BB*NN*2)
#define OFF3 (OFF2 + BB*NN*4)
#define OFF4 (OFF3 + BB*NN*CC)
#define OFF5 (OFF4 + BB*NN*4)
#define OFF6 (OFF5 + BB*NN*CC)

// ---- scratch (device globals; zero-initialized at module load; no allocation) ----
__device__ int                g_cnt[BB*CC];          // bucket counters; nms resets after reading
__device__ unsigned long long g_bkey[BB*CC*CAP];     // composite keys per bucket
__device__ float4             g_bbox[BB*CC*CAP];     // offset boxes per bucket (same slot as key)

// reduction input may arrive as int32 or float32; handle both.
__device__ __forceinline__ float read_reduction(const void* p) {
    if (p == nullptr) return 16.0f;
    int iv = *(const int*)p;
    if (iv > 0 && iv < (1 << 20)) return (float)iv;
    return *(const float*)p;
}

// ============================================================
// Kernel 1: per-row prep, one warp per TWO rows (ILP x2).
// Identical math to the proven 33.5us version; additionally
// stores the offset box next to the bucket key so NMS needs no
// gather from the output tensor.
// ============================================================
__global__ __launch_bounds__(256)
void prep_kernel(const float* __restrict__ nms_reg,
                 const float* __restrict__ nms_cls,
                 const float* __restrict__ rcnn_reg,
                 const float* __restrict__ rcnn_cls,
                 const void* __restrict__ redp,
                 float* __restrict__ out)
{
    const int gw   = (blockIdx.x * blockDim.x + threadIdx.x) >> 5;
    const int lane = threadIdx.x & 31;
    const int row0 = gw * 2;
    if (row0 >= NROWS) return;
    const int row1 = row0 + 1;

    const bool has2 = (lane < CC - 64);
    const float* cl0 = rcnn_cls + (size_t)row0 * CC;
    const float* cl1 = cl0 + CC;

    float a0 = cl0[lane];
    float a1 = cl0[lane + 32];
    float a2 = has2 ? cl0[lane + 64] : -INFINITY;
    float b0 = cl1[lane];
    float b1 = cl1[lane + 32];
    float b2 = has2 ? cl1[lane + 64] : -INFINITY;

    float mA = fmaxf(a0, fmaxf(a1, a2));
    float mB = fmaxf(b0, fmaxf(b1, b2));
    #pragma unroll
    for (int o = 16; o; o >>= 1) {
        mA = fmaxf(mA, __shfl_xor_sync(0xFFFFFFFFu, mA, o));
        mB = fmaxf(mB, __shfl_xor_sync(0xFFFFFFFFu, mB, o));
    }

    float eA0 = expf(a0 - mA), eA1 = expf(a1 - mA), eA2 = has2 ? expf(a2 - mA) : 0.0f;
    float eB0 = expf(b0 - mB), eB1 = expf(b1 - mB), eB2 = has2 ? expf(b2 - mB) : 0.0f;
    float sA = eA0 + eA1 + eA2;
    float sB = eB0 + eB1 + eB2;
    #pragma unroll
    for (int o = 16; o; o >>= 1) {
        sA += __shfl_xor_sync(0xFFFFFFFFu, sA, o);
        sB += __shfl_xor_sync(0xFFFFFFFFu, sB, o);
    }

    float pA0 = eA0 / sA, pA1 = eA1 / sA, pA2 = eA2 / sA;
    float pB0 = eB0 / sB, pB1 = eB1 / sB, pB2 = eB2 / sB;

    float* poA = out + OFF3 + (size_t)row0 * CC;
    float* poB = poA + CC;
    poA[lane]      = pA0;
    poA[lane + 32] = pA1;
    if (has2) poA[lane + 64] = pA2;
    poB[lane]      = pB0;
    poB[lane + 32] = pB1;
    if (has2) poB[lane + 64] = pB2;

    float bpA = pA0; int biA = lane;
    if (pA1 > bpA) { bpA = pA1; biA = lane + 32; }
    if (has2 && pA2 > bpA) { bpA = pA2; biA = lane + 64; }
    float bpB = pB0; int biB = lane;
    if (pB1 > bpB) { bpB = pB1; biB = lane + 32; }
    if (has2 && pB2 > bpB) { bpB = pB2; biB = lane + 64; }
    #pragma unroll
    for (int o = 16; o; o >>= 1) {
        float opA = __shfl_xor_sync(0xFFFFFFFFu, bpA, o);
        int   oiA = __shfl_xor_sync(0xFFFFFFFFu, biA, o);
        if (opA > bpA || (opA == bpA && oiA < biA)) { bpA = opA; biA = oiA; }
        float opB = __shfl_xor_sync(0xFFFFFFFFu, bpB, o);
        int   oiB = __shfl_xor_sync(0xFFFFFFFFu, biB, o);
        if (opB > bpB || (opB == bpB && oiB < biB)) { bpB = opB; biB = oiB; }
    }

    const float kA = (biA != 0) ? 1.0f : 0.0f;
    const float kB = (biB != 0) ? 1.0f : 0.0f;

    float* coA = out + OFF5 + (size_t)row0 * CC;
    float* coB = coA + CC;
    coA[lane]      = pA0 * kA;
    coA[lane + 32] = pA1 * kA;
    if (has2) coA[lane + 64] = pA2 * kA;
    coB[lane]      = pB0 * kB;
    coB[lane + 32] = pB1 * kB;
    if (has2) coB[lane + 64] = pB2 * kB;

    if (lane < 2) {
        const int   row = (lane == 0) ? row0 : row1;
        const int   cls = (lane == 0) ? biA  : biB;
        const float bp  = (lane == 0) ? bpA  : bpB;
        const float k   = (lane == 0) ? kA   : kB;
        const float red = read_reduction(redp);

        float4 nr = ((const float4*)nms_reg)[row];
        float rt = floorf(nr.x * red) / red;
        float rl = floorf(nr.y * red) / red;
        float rb = ceilf(nr.z * red) / red;
        float rr = ceilf(nr.w * red) / red;

        float4 rg = ((const float4*)rcnn_reg)[row];
        float4 adj;
        adj.x = rg.x + rt; adj.y = rg.y + rl; adj.z = rg.z + rb; adj.w = rg.w + rr;
        ((float4*)(out + OFF2))[row] = adj;

        float4 ro;
        ro.x = adj.x * k; ro.y = adj.y * k; ro.z = adj.z * k; ro.w = adj.w * k;
        ((float4*)(out + OFF4))[row] = ro;

        ((float4*)(out + OFF0))[row] = nr;
        ((float2*)(out + OFF1))[row] = ((const float2*)nms_cls)[row];

        out[OFF6 + row] = k;

        if (cls != 0) {
            unsigned sb = __float_as_uint(bp);
            unsigned so = (sb & 0x80000000u) ? ~sb : (sb | 0x80000000u);
            unsigned sdesc = ~so;
            int b = row / NN, n = row % NN;
            unsigned long long key = ((unsigned long long)sdesc << 32)
                                   | (unsigned long long)(unsigned)n;
            int bc = b * CC + cls;
            int pos = atomicAdd(&g_cnt[bc], 1);
            if (pos < CAP) {
                size_t slot = (size_t)bc * CAP + pos;
                g_bkey[slot] = key;
                float off = (float)cls * CLASS_OFFSET;
                float4 ob;
                ob.x = adj.x + off; ob.y = adj.y + off;
                ob.z = adj.z + off; ob.w = adj.w + off;
                g_bbox[slot] = ob;
            }
        }
    }
}

// ============================================================
// Kernel 2: block-per-task bitmask NMS (256 threads = 8 warps).
//  A: thread-parallel key load + rank sort + box placement.
//  B: suppression-matrix rows split across 8 warps (independent).
//  C: warp-0 serial bit resolution in registers.
//  D: suppressed-row fixup split across warps.
// Greedy semantics identical to reference (cross-class IoU = 0).
// ============================================================
#define NTPB 256
__global__ __launch_bounds__(NTPB)
void nms_kernel(float* __restrict__ out)
{
    const int task = blockIdx.x;                 // 0..639
    const int tid  = threadIdx.x;
    const int lane = tid & 31;
    const int wid  = tid >> 5;                   // 0..7

    const int b  = task / (CC - 1);
    const int c  = task % (CC - 1) + 1;
    const int bc = b * CC + c;

    __shared__ unsigned long long s_key[CAP];
    __shared__ float4             s_box[CAP];
    __shared__ unsigned short     s_sid[CAP];
    __shared__ uint4              s_rm [CAP];
    __shared__ unsigned           s_keepw[3];

    int n = g_cnt[bc];
    if (n > CAP) n = CAP;

    // ---- Phase A: load keys (all threads read n first, then reset) ----
    const size_t base = (size_t)bc * CAP;
    if (tid < n) s_key[tid] = g_bkey[base + tid];
    __syncthreads();
    if (tid == 0) g_cnt[bc] = 0;                 // reset for next replay

    if (n <= 0) return;

    // rank sort + box placement (keys unique via idx low bits)
    if (tid < n) {
        unsigned long long kj = s_key[tid];
        int rank = 0;
        for (int kk = 0; kk < n; kk++) rank += (s_key[kk] < kj);
        s_sid[rank] = (unsigned short)(kj & 0xFFFFFFFFu);
        s_box[rank] = g_bbox[base + tid];
    }
    __syncthreads();

    // ---- Phase B: suppression matrix, rows split across warps ----
    {
        float4 bx0, bx1, bx2;
        float ar0 = 0.0f, ar1 = 0.0f, ar2 = 0.0f;
        if (lane < n)      { bx0 = s_box[lane];      ar0 = (bx0.z - bx0.x) * (bx0.w - bx0.y); }
        if (lane + 32 < n) { bx1 = s_box[lane + 32]; ar1 = (bx1.z - bx1.x) * (bx1.w - bx1.y); }
        if (lane + 64 < n) { bx2 = s_box[lane + 64]; ar2 = (bx2.z - bx2.x) * (bx2.w - bx2.y); }

        for (int i = wid; i < n - 1; i += NTPB / 32) {
            float4 bi = s_box[i];
            float areai = (bi.z - bi.x) * (bi.w - bi.y);

            bool sup0 = false, sup1 = false, sup2 = false;
            {
                int j = lane;
                if (j < n && j > i) {
                    float it = fmaxf(bi.x, bx0.x);
                    float il = fmaxf(bi.y, bx0.y);
                    float ib = fminf(bi.z, bx0.z);
                    float ir = fminf(bi.w, bx0.w);
                    float inter = fmaxf(ib - it, 0.0f) * fmaxf(ir - il, 0.0f);
                    float uni = areai + ar0 - inter;
                    float iou = inter / fmaxf(uni, 1e-9f);
                    sup0 = (iou > IOU_THR);
                }
            }
            unsigned w0 = __ballot_sync(0xFFFFFFFFu, sup0);
            unsigned w1 = 0, w2 = 0;
            if (n > 32) {
                int j = lane + 32;
                if (j < n && j > i) {
                    float it = fmaxf(bi.x, bx1.x);
                    float il = fmaxf(bi.y, bx1.y);
                    float ib = fminf(bi.z, bx1.z);
                    float ir = fminf(bi.w, bx1.w);
                    float inter = fmaxf(ib - it, 0.0f) * fmaxf(ir - il, 0.0f);
                    float uni = areai + ar1 - inter;
                    float iou = inter / fmaxf(uni, 1e-9f);
                    sup1 = (iou > IOU_THR);
                }
                w1 = __ballot_sync(0xFFFFFFFFu, sup1);
            }
            if (n > 64) {
                int j = lane + 64;
                if (j < n && j > i) {
                    float it = fmaxf(bi.x, bx2.x);
                    float il = fmaxf(bi.y, bx2.y);
                    float ib = fminf(bi.z, bx2.z);
                    float ir = fminf(bi.w, bx2.w);
                    float inter = fmaxf(ib - it, 0.0f) * fmaxf(ir - il, 0.0f);
                    float uni = areai + ar2 - inter;
                    float iou = inter / fmaxf(uni, 1e-9f);
                    sup2 = (iou > IOU_THR);
                }
                w2 = __ballot_sync(0xFFFFFFFFu, sup2);
            }
            if (lane == 0) {
                uint4 rm; rm.x = w0; rm.y = w1; rm.z = w2; rm.w = 0;
                s_rm[i] = rm;
            }
        }
    }
    __syncthreads();

    // ---- Phase C: serial bit resolution (warp 0, registers) ----
    if (wid == 0) {
        unsigned k0, k1, k2;
        k0 = (n >= 32) ? 0xFFFFFFFFu : ((1u << n) - 1u);
        k1 = (n >= 64) ? 0xFFFFFFFFu : ((n > 32) ? ((1u << (n - 32)) - 1u) : 0u);
        k2 = (n > 64) ? ((n >= 96) ? 0xFFFFFFFFu : ((1u << (n - 64)) - 1u)) : 0u;

        for (int i = 0; i < n - 1; i++) {
            unsigned word = (i < 32) ? k0 : ((i < 64) ? k1 : k2);
            if ((word >> (i & 31)) & 1u) {
                uint4 rm = s_rm[i];
                k0 &= ~rm.x; k1 &= ~rm.y; k2 &= ~rm.z;
            }
        }
        if (lane == 0) { s_keepw[0] = k0; s_keepw[1] = k1; s_keepw[2] = k2; }
    }
    __syncthreads();

    // ---- Phase D: fixup suppressed rows, split across warps ----
    for (int i = wid; i < n; i += NTPB / 32) {
        unsigned word = s_keepw[i >> 5];
        if (!((word >> (i & 31)) & 1u)) {
            int row = b * NN + (int)s_sid[i];
            float* co = out + OFF5 + (size_t)row * CC;
            co[lane]      = 0.0f;
            co[lane + 32] = 0.0f;
            if (lane < CC - 64) co[lane + 64] = 0.0f;
            if (lane == 0) {
                float4 z; z.x = 0.0f; z.y = 0.0f; z.z = 0.0f; z.w = 0.0f;
                ((float4*)(out + OFF4))[row] = z;
                out[OFF6 + row] = 0.0f;
            }
        }
    }
}

extern "C" void kernel_launch(void* const* d_in, const int* in_sizes, int n_in,
                              void* d_out, int out_size)
{
    const float* nms_reg  = (const float*)d_in[0];
    const float* nms_cls  = (const float*)d_in[1];
    const float* rcnn_reg = (const float*)d_in[2];
    const float* rcnn_cls = (const float*)d_in[3];
    const void*  redp     = (n_in >= 5) ? d_in[4] : nullptr;
    float* out = (float*)d_out;
    (void)in_sizes; (void)out_size;

    const int warps = NROWS / 2;
    const int tpb = 256;
    const int blocks = (warps * 32 + tpb - 1) / tpb;   // 1000
    prep_kernel<<<blocks, tpb>>>(nms_reg, nms_cls, rcnn_reg, rcnn_cls, redp, out);

    nms_kernel<<<NTASK, NTPB>>>(out);
}

// round 8
// speedup vs baseline: 2.4189x; 1.1302x over previous
#include <cuda_runtime.h>
#include <cuda_bf16.h>
#include <math.h>

// Problem constants (fixed by the dataset)
#define BB 8
#define NN 2000
#define CC 81
#define IOU_THR 0.5f
#define CLASS_OFFSET 100000.0f
#define CAP 96                  // per-(batch,class) bucket capacity (mean ~25, +14 sigma)
#define NROWS (BB * NN)         // 16000
#define NTASK (BB * (CC - 1))   // 640 NMS tasks

// Output layout: concat of reference's 7-tuple, all float32
// (nms_reg, nms_cls, rcnn_reg_adj, probs, reg_out, cls_out, keep)
#define OFF0 0
#define OFF1 (BB*NN*4)
#define OFF2 (OFF1 + BB*NN*2)
#define OFF3 (OFF2 + BB*NN*4)
#define OFF4 (OFF3 + BB*NN*CC)
#define OFF5 (OFF4 + BB*NN*4)
#define OFF6 (OFF5 + BB*NN*CC)

// ---- scratch (device globals; zero-initialized at module load; no allocation) ----
__device__ int                g_cnt[BB*CC];          // bucket counters; nms resets after reading
__device__ unsigned long long g_bkey[BB*CC*CAP];     // composite keys per bucket
__device__ float4             g_bbox[BB*CC*CAP];     // offset boxes per bucket (same slot as key)

// reduction input may arrive as int32 or float32; handle both.
__device__ __forceinline__ float read_reduction(const void* p) {
    if (p == nullptr) return 16.0f;
    int iv = *(const int*)p;
    if (iv > 0 && iv < (1 << 20)) return (float)iv;
    return *(const float*)p;
}

// ============================================================
// Kernel 1: per-row prep, one warp per TWO rows (ILP x2).
// (identical math to the proven passing versions)
// ============================================================
__global__ __launch_bounds__(256)
void prep_kernel(const float* __restrict__ nms_reg,
                 const float* __restrict__ nms_cls,
                 const float* __restrict__ rcnn_reg,
                 const float* __restrict__ rcnn_cls,
                 const void* __restrict__ redp,
                 float* __restrict__ out)
{
    const int gw   = (blockIdx.x * blockDim.x + threadIdx.x) >> 5;
    const int lane = threadIdx.x & 31;
    const int row0 = gw * 2;
    if (row0 >= NROWS) return;
    const int row1 = row0 + 1;

    const bool has2 = (lane < CC - 64);
    const float* cl0 = rcnn_cls + (size_t)row0 * CC;
    const float* cl1 = cl0 + CC;

    float a0 = cl0[lane];
    float a1 = cl0[lane + 32];
    float a2 = has2 ? cl0[lane + 64] : -INFINITY;
    float b0 = cl1[lane];
    float b1 = cl1[lane + 32];
    float b2 = has2 ? cl1[lane + 64] : -INFINITY;

    float mA = fmaxf(a0, fmaxf(a1, a2));
    float mB = fmaxf(b0, fmaxf(b1, b2));
    #pragma unroll
    for (int o = 16; o; o >>= 1) {
        mA = fmaxf(mA, __shfl_xor_sync(0xFFFFFFFFu, mA, o));
        mB = fmaxf(mB, __shfl_xor_sync(0xFFFFFFFFu, mB, o));
    }

    float eA0 = expf(a0 - mA), eA1 = expf(a1 - mA), eA2 = has2 ? expf(a2 - mA) : 0.0f;
    float eB0 = expf(b0 - mB), eB1 = expf(b1 - mB), eB2 = has2 ? expf(b2 - mB) : 0.0f;
    float sA = eA0 + eA1 + eA2;
    float sB = eB0 + eB1 + eB2;
    #pragma unroll
    for (int o = 16; o; o >>= 1) {
        sA += __shfl_xor_sync(0xFFFFFFFFu, sA, o);
        sB += __shfl_xor_sync(0xFFFFFFFFu, sB, o);
    }

    float pA0 = eA0 / sA, pA1 = eA1 / sA, pA2 = eA2 / sA;
    float pB0 = eB0 / sB, pB1 = eB1 / sB, pB2 = eB2 / sB;

    float* poA = out + OFF3 + (size_t)row0 * CC;
    float* poB = poA + CC;
    poA[lane]      = pA0;
    poA[lane + 32] = pA1;
    if (has2) poA[lane + 64] = pA2;
    poB[lane]      = pB0;
    poB[lane + 32] = pB1;
    if (has2) poB[lane + 64] = pB2;

    float bpA = pA0; int biA = lane;
    if (pA1 > bpA) { bpA = pA1; biA = lane + 32; }
    if (has2 && pA2 > bpA) { bpA = pA2; biA = lane + 64; }
    float bpB = pB0; int biB = lane;
    if (pB1 > bpB) { bpB = pB1; biB = lane + 32; }
    if (has2 && pB2 > bpB) { bpB = pB2; biB = lane + 64; }
    #pragma unroll
    for (int o = 16; o; o >>= 1) {
        float opA = __shfl_xor_sync(0xFFFFFFFFu, bpA, o);
        int   oiA = __shfl_xor_sync(0xFFFFFFFFu, biA, o);
        if (opA > bpA || (opA == bpA && oiA < biA)) { bpA = opA; biA = oiA; }
        float opB = __shfl_xor_sync(0xFFFFFFFFu, bpB, o);
        int   oiB = __shfl_xor_sync(0xFFFFFFFFu, biB, o);
        if (opB > bpB || (opB == bpB && oiB < biB)) { bpB = opB; biB = oiB; }
    }

    const float kA = (biA != 0) ? 1.0f : 0.0f;
    const float kB = (biB != 0) ? 1.0f : 0.0f;

    float* coA = out + OFF5 + (size_t)row0 * CC;
    float* coB = coA + CC;
    coA[lane]      = pA0 * kA;
    coA[lane + 32] = pA1 * kA;
    if (has2) coA[lane + 64] = pA2 * kA;
    coB[lane]      = pB0 * kB;
    coB[lane + 32] = pB1 * kB;
    if (has2) coB[lane + 64] = pB2 * kB;

    if (lane < 2) {
        const int   row = (lane == 0) ? row0 : row1;
        const int   cls = (lane == 0) ? biA  : biB;
        const float bp  = (lane == 0) ? bpA  : bpB;
        const float k   = (lane == 0) ? kA   : kB;
        const float red = read_reduction(redp);

        float4 nr = ((const float4*)nms_reg)[row];
        float rt = floorf(nr.x * red) / red;
        float rl = floorf(nr.y * red) / red;
        float rb = ceilf(nr.z * red) / red;
        float rr = ceilf(nr.w * red) / red;

        float4 rg = ((const float4*)rcnn_reg)[row];
        float4 adj;
        adj.x = rg.x + rt; adj.y = rg.y + rl; adj.z = rg.z + rb; adj.w = rg.w + rr;
        ((float4*)(out + OFF2))[row] = adj;

        float4 ro;
        ro.x = adj.x * k; ro.y = adj.y * k; ro.z = adj.z * k; ro.w = adj.w * k;
        ((float4*)(out + OFF4))[row] = ro;

        ((float4*)(out + OFF0))[row] = nr;
        ((float2*)(out + OFF1))[row] = ((const float2*)nms_cls)[row];

        out[OFF6 + row] = k;

        if (cls != 0) {
            unsigned sb = __float_as_uint(bp);
            unsigned so = (sb & 0x80000000u) ? ~sb : (sb | 0x80000000u);
            unsigned sdesc = ~so;
            int b = row / NN, n = row % NN;
            unsigned long long key = ((unsigned long long)sdesc << 32)
                                   | (unsigned long long)(unsigned)n;
            int bc = b * CC + cls;
            int pos = atomicAdd(&g_cnt[bc], 1);
            if (pos < CAP) {
                size_t slot = (size_t)bc * CAP + pos;
                g_bkey[slot] = key;
                float off = (float)cls * CLASS_OFFSET;
                float4 ob;
                ob.x = adj.x + off; ob.y = adj.y + off;
                ob.z = adj.z + off; ob.w = adj.w + off;
                g_bbox[slot] = ob;
            }
        }
    }
}

// ============================================================
// Kernel 2: block-per-task bitmask NMS (256 threads = 8 warps).
// Chain-shortened: g_cnt / g_bkey / g_bbox loads all issued
// speculatively in parallel at entry; no-suppression early exit
// skips the serial resolution + fixup entirely.
// Greedy semantics identical to reference (cross-class IoU = 0).
// ============================================================
#define NTPB 256
__global__ __launch_bounds__(NTPB)
void nms_kernel(float* __restrict__ out)
{
    const int task = blockIdx.x;                 // 0..639
    const int tid  = threadIdx.x;
    const int lane = tid & 31;
    const int wid  = tid >> 5;                   // 0..7

    const int b  = task / (CC - 1);
    const int c  = task % (CC - 1) + 1;
    const int bc = b * CC + c;

    __shared__ unsigned long long s_key[CAP];
    __shared__ float4             s_box[CAP];
    __shared__ unsigned short     s_sid[CAP];
    __shared__ uint4              s_rm [CAP];
    __shared__ unsigned           s_keepw[3];
    __shared__ int                s_anysup;

    // ---- speculative parallel loads (independent; all overlap) ----
    const size_t base = (size_t)bc * CAP;
    unsigned long long mykey = 0ull;
    float4 mybox;
    if (tid < CAP) {
        mykey = g_bkey[base + tid];
        mybox = g_bbox[base + tid];
    }
    int n = g_cnt[bc];
    if (n > CAP) n = CAP;

    if (tid < n) s_key[tid] = mykey;
    if (tid == 0) { s_anysup = 0; }
    __syncthreads();
    if (tid == 0) g_cnt[bc] = 0;                 // reset for next replay

    if (n <= 0) return;

    // rank sort + box placement (keys unique via idx low bits)
    if (tid < n) {
        int rank = 0;
        for (int kk = 0; kk < n; kk++) rank += (s_key[kk] < mykey);
        s_sid[rank] = (unsigned short)(mykey & 0xFFFFFFFFu);
        s_box[rank] = mybox;
    }
    __syncthreads();

    // ---- Phase B: suppression matrix, rows split across warps ----
    {
        float4 bx0, bx1, bx2;
        float ar0 = 0.0f, ar1 = 0.0f, ar2 = 0.0f;
        if (lane < n)      { bx0 = s_box[lane];      ar0 = (bx0.z - bx0.x) * (bx0.w - bx0.y); }
        if (lane + 32 < n) { bx1 = s_box[lane + 32]; ar1 = (bx1.z - bx1.x) * (bx1.w - bx1.y); }
        if (lane + 64 < n) { bx2 = s_box[lane + 64]; ar2 = (bx2.z - bx2.x) * (bx2.w - bx2.y); }

        bool any = false;
        for (int i = wid; i < n - 1; i += NTPB / 32) {
            float4 bi = s_box[i];
            float areai = (bi.z - bi.x) * (bi.w - bi.y);

            bool sup0 = false, sup1 = false, sup2 = false;
            {
                int j = lane;
                if (j < n && j > i) {
                    float it = fmaxf(bi.x, bx0.x);
                    float il = fmaxf(bi.y, bx0.y);
                    float ib = fminf(bi.z, bx0.z);
                    float ir = fminf(bi.w, bx0.w);
                    float inter = fmaxf(ib - it, 0.0f) * fmaxf(ir - il, 0.0f);
                    float uni = areai + ar0 - inter;
                    float iou = inter / fmaxf(uni, 1e-9f);
                    sup0 = (iou > IOU_THR);
                }
            }
            unsigned w0 = __ballot_sync(0xFFFFFFFFu, sup0);
            unsigned w1 = 0, w2 = 0;
            if (n > 32) {
                int j = lane + 32;
                if (j < n && j > i) {
                    float it = fmaxf(bi.x, bx1.x);
                    float il = fmaxf(bi.y, bx1.y);
                    float ib = fminf(bi.z, bx1.z);
                    float ir = fminf(bi.w, bx1.w);
                    float inter = fmaxf(ib - it, 0.0f) * fmaxf(ir - il, 0.0f);
                    float uni = areai + ar1 - inter;
                    float iou = inter / fmaxf(uni, 1e-9f);
                    sup1 = (iou > IOU_THR);
                }
                w1 = __ballot_sync(0xFFFFFFFFu, sup1);
            }
            if (n > 64) {
                int j = lane + 64;
                if (j < n && j > i) {
                    float it = fmaxf(bi.x, bx2.x);
                    float il = fmaxf(bi.y, bx2.y);
                    float ib = fminf(bi.z, bx2.z);
                    float ir = fminf(bi.w, bx2.w);
                    float inter = fmaxf(ib - it, 0.0f) * fmaxf(ir - il, 0.0f);
                    float uni = areai + ar2 - inter;
                    float iou = inter / fmaxf(uni, 1e-9f);
                    sup2 = (iou > IOU_THR);
                }
                w2 = __ballot_sync(0xFFFFFFFFu, sup2);
            }
            if (lane == 0) {
                uint4 rm; rm.x = w0; rm.y = w1; rm.z = w2; rm.w = 0;
                s_rm[i] = rm;
                if ((w0 | w1 | w2) != 0u) any = true;
            }
        }
        if (any) s_anysup = 1;     // benign race; only 1s written
    }
    __syncthreads();

    // ---- no-suppression early exit: speculative outputs already final ----
    if (s_anysup == 0) return;

    // ---- Phase C: serial bit resolution (warp 0, registers) ----
    if (wid == 0) {
        unsigned k0, k1, k2;
        k0 = (n >= 32) ? 0xFFFFFFFFu : ((1u << n) - 1u);
        k1 = (n >= 64) ? 0xFFFFFFFFu : ((n > 32) ? ((1u << (n - 32)) - 1u) : 0u);
        k2 = (n > 64) ? ((n >= 96) ? 0xFFFFFFFFu : ((1u << (n - 64)) - 1u)) : 0u;

        for (int i = 0; i < n - 1; i++) {
            unsigned word = (i < 32) ? k0 : ((i < 64) ? k1 : k2);
            if ((word >> (i & 31)) & 1u) {
                uint4 rm = s_rm[i];
                k0 &= ~rm.x; k1 &= ~rm.y; k2 &= ~rm.z;
            }
        }
        if (lane == 0) { s_keepw[0] = k0; s_keepw[1] = k1; s_keepw[2] = k2; }
    }
    __syncthreads();

    // ---- Phase D: fixup suppressed rows, split across warps ----
    for (int i = wid; i < n; i += NTPB / 32) {
        unsigned word = s_keepw[i >> 5];
        if (!((word >> (i & 31)) & 1u)) {
            int row = b * NN + (int)s_sid[i];
            float* co = out + OFF5 + (size_t)row * CC;
            co[lane]      = 0.0f;
            co[lane + 32] = 0.0f;
            if (lane < CC - 64) co[lane + 64] = 0.0f;
            if (lane == 0) {
                float4 z; z.x = 0.0f; z.y = 0.0f; z.z = 0.0f; z.w = 0.0f;
                ((float4*)(out + OFF4))[row] = z;
                out[OFF6 + row] = 0.0f;
            }
        }
    }
}

extern "C" void kernel_launch(void* const* d_in, const int* in_sizes, int n_in,
                              void* d_out, int out_size)
{
    const float* nms_reg  = (const float*)d_in[0];
    const float* nms_cls  = (const float*)d_in[1];
    const float* rcnn_reg = (const float*)d_in[2];
    const float* rcnn_cls = (const float*)d_in[3];
    const void*  redp     = (n_in >= 5) ? d_in[4] : nullptr;
    float* out = (float*)d_out;
    (void)in_sizes; (void)out_size;

    const int warps = NROWS / 2;
    const int tpb = 256;
    const int blocks = (warps * 32 + tpb - 1) / tpb;   // 1000
    prep_kernel<<<blocks, tpb>>>(nms_reg, nms_cls, rcnn_reg, rcnn_cls, redp, out);

    nms_kernel<<<NTASK, NTPB>>>(out);
}